// round 5
// baseline (speedup 1.0000x reference)
#include <cuda_runtime.h>
#include <cuda_bf16.h>
#include <cstdint>
#include <math.h>
#include <math_constants.h>

// ===========================================================================
// RecurrenceAttention — bf16 mma.sync, all-bf16 operands, 64-row warp tiles.
//
//  cvt_bf16   : Wq/Wkv/Wfc -> bf16 (once per launch; deterministic)
//  concat_h   : h = [mem ; x] bf16         (x reused from h for G0's A)
//  fill_pos   : B2 pos half ; zero_a2row
//  G0         : q = x@Wq^T   -> A2 bf16 (q+u | shifted q+v)
//  G1         : kv = h@Wkv^T -> B2 bf16 k-half + Vt bf16 ([bz][d][j])
//  G2         : S = A2@B2^T  (batched 32, K=128) -> S bf16 (mask+scale);
//               fully-masked tiles skipped entirely (never read)
//  colstats2  : pass1 per-col stats; pass2 rewrites S in place as
//               P = exp(S-M)/Z bf16, zeroing the masked margin
//  G3         : out = P @ Vt^T (pure bf16 GEMM, masked K-chunks skipped)
//  G4         : y = of@Wfc^T + x + bfc  (fp32 out)
//  ln_kernel  : LayerNorm -> d_out
// ===========================================================================

// ---------------- scratch ----------------
__device__ __nv_bfloat16 g_h   [4096 * 1024];
__device__ __nv_bfloat16 g_Wqb [1024 * 1024];
__device__ __nv_bfloat16 g_Wkvb[2048 * 1024];
__device__ __nv_bfloat16 g_Wfcb[1024 * 1024];
__device__ __nv_bfloat16 g_A2  [32 * 1024 * 128];
__device__ __nv_bfloat16 g_B2  [32 * 2048 * 128];
__device__ __nv_bfloat16 g_V   [32 * 64 * 2048];       // [bz][d][j]
__device__ __nv_bfloat16 g_S   [32u * 1024u * 2048u];  // S, then P in place
__device__ __nv_bfloat16 g_of  [2048 * 1024];
__device__ float g_y [2048 * 1024];

// ---------------- helpers ----------------
__device__ __forceinline__ uint32_t smem_u32(const void* p) {
    uint32_t a;
    asm("{ .reg .u64 t; cvta.to.shared.u64 t, %1; cvt.u32.u64 %0, t; }"
        : "=r"(a) : "l"(p));
    return a;
}
__device__ __forceinline__ uint32_t pack_bf2(float a, float b) {
    __nv_bfloat162 h = __float22bfloat162_rn(make_float2(a, b));
    return *reinterpret_cast<uint32_t*>(&h);
}
__device__ __forceinline__ void ldsm4(uint32_t* r, uint32_t addr) {
    asm volatile("ldmatrix.sync.aligned.m8n8.x4.shared.b16 {%0,%1,%2,%3}, [%4];"
                 : "=r"(r[0]), "=r"(r[1]), "=r"(r[2]), "=r"(r[3]) : "r"(addr));
}
__device__ __forceinline__ void mma16(float* c, const uint32_t* a,
                                      uint32_t b0, uint32_t b1) {
    asm volatile(
        "mma.sync.aligned.m16n8k16.row.col.f32.bf16.bf16.f32 "
        "{%0,%1,%2,%3}, {%4,%5,%6,%7}, {%8,%9}, {%0,%1,%2,%3};"
        : "+f"(c[0]), "+f"(c[1]), "+f"(c[2]), "+f"(c[3])
        : "r"(a[0]), "r"(a[1]), "r"(a[2]), "r"(a[3]), "r"(b0), "r"(b1));
}

// fast exp on FMA pipe
__device__ __forceinline__ float fexp(float x) {
    float y = fmaxf(x * 1.4426950408889634f, -126.0f);
    float fn = floorf(y);
    float f  = y - fn;
    float p  = 1.5403530e-4f;
    p = fmaf(p, f, 1.3333558e-3f);
    p = fmaf(p, f, 9.6181291e-3f);
    p = fmaf(p, f, 5.5504109e-2f);
    p = fmaf(p, f, 2.4022651e-1f);
    p = fmaf(p, f, 6.9314718e-1f);
    p = fmaf(p, f, 1.0f);
    return p * __int_as_float(((int)fn + 127) << 23);
}

// ---------------- small kernels ----------------
__global__ __launch_bounds__(256) void cvt_bf16(const float* __restrict__ src,
                                                __nv_bfloat16* __restrict__ dst) {
    size_t i = (size_t)blockIdx.x * 256 + threadIdx.x;   // 4 floats per item
    float4 v = reinterpret_cast<const float4*>(src)[i];
    uint2 o;
    o.x = pack_bf2(v.x, v.y);
    o.y = pack_bf2(v.z, v.w);
    *reinterpret_cast<uint2*>(dst + i * 4) = o;
}

__global__ __launch_bounds__(256) void concat_h(const float* __restrict__ x,
                                                const float* __restrict__ mem) {
    size_t idx = (size_t)blockIdx.x * 256 + threadIdx.x;
    size_t r   = idx >> 8;
    int    c4  = (int)(idx & 255);
    int beta = (int)(r >> 11);
    int s    = (int)(r & 2047);
    const float* src = (s < 1024)
        ? mem + ((size_t)(beta * 1024 + s)) * 1024
        : x   + ((size_t)(beta * 1024 + s - 1024)) * 1024;
    float4 v = reinterpret_cast<const float4*>(src)[c4];
    uint2 o;
    o.x = pack_bf2(v.x, v.y);
    o.y = pack_bf2(v.z, v.w);
    *reinterpret_cast<uint2*>(g_h + idx * 4) = o;
}

__global__ __launch_bounds__(256) void fill_pos(const float* __restrict__ pos_emb) {
    int idx = blockIdx.x * 256 + threadIdx.x;
    int d4 = idx & 15;
    int j  = (idx >> 4) & 2047;
    int bz = idx >> 15;
    int hh = bz & 15;
    float4 p = *reinterpret_cast<const float4*>(pos_emb + (size_t)j * 1024 + hh * 64 + d4 * 4);
    uint2 o;
    o.x = pack_bf2(p.x, p.y);
    o.y = pack_bf2(p.z, p.w);
    *reinterpret_cast<uint2*>(g_B2 + (((size_t)bz * 2048 + j) * 128) + 64 + d4 * 4) = o;
}

__global__ __launch_bounds__(256) void zero_a2row() {
    int t = blockIdx.x * 256 + threadIdx.x;
    int hh = t >> 6, d = t & 63;
    g_A2[(((size_t)hh) * 1024 + 1023) * 128 + 64 + d] = __float2bfloat16(0.0f);
}

// ---------------------------------------------------------------------------
// bf16 GEMM: D(M x N) = A(M x K) * B(N x K)^T, K-major bf16 inputs.
// BM=128, warp tile 64 x WN. NWARP in {4, 8}; warp grid 2 x (NWARP/2).
// SMEM rows padded to 80B (conflict-free ldmatrix). Double-buffered, BK=32.
// MODE: 0=qproj(A rows remapped into g_h)  1=kvproj  2=scores  3=P@V  4=fc
// ---------------------------------------------------------------------------
template <int MODE, int BN, int NWARP>
__global__ __launch_bounds__(NWARP * 32, NWARP == 4 ? 3 : 2)
void gemm_bf16(const __nv_bfloat16* __restrict__ Ag,
               const __nv_bfloat16* __restrict__ Bg, int K,
               size_t batchA, size_t batchB,
               const float* __restrict__ aux0, const float* __restrict__ aux1,
               void* __restrict__ D0v, void* __restrict__ D1v) {
    constexpr int THREADS = NWARP * 32;
    constexpr int WCOLS   = NWARP / 2;
    constexpr int WN      = BN / WCOLS;       // warp tile cols
    constexpr int NT      = WN / 8;
    constexpr int NG      = WN / 16;
    constexpr int APASS   = 512 / THREADS;    // A uint4 loads per thread
    constexpr int BPASS   = (BN * 4) / THREADS;
    constexpr int LOG2BN  = (BN == 64) ? 6 : 7;

    __shared__ __align__(16) uint8_t sA[2][128 * 80];
    __shared__ __align__(16) uint8_t sB[2][BN * 80];

    const int t    = threadIdx.x;
    const int wid  = t >> 5;
    const int lane = t & 31;
    const int wm   = wid / WCOLS;             // 0..1
    const int wn   = wid % WCOLS;
    const int group = lane >> 2;
    const int tid4  = lane & 3;
    const int rowBase = blockIdx.y * 128;
    const int colBase = blockIdx.x * BN;

    // fully-masked score tiles: nothing downstream reads them — just exit
    if (MODE == 2 && colBase > rowBase + 1151) return;

    const __nv_bfloat16* A = Ag + (size_t)blockIdx.z * batchA;
    const __nv_bfloat16* B = Bg + (size_t)blockIdx.z * batchB;

    int nch = K >> 5;
    if (MODE == 3) {
        int lim = ((rowBase + 1151) >> 5) + 1;   // skip fully-masked K-chunks
        if (lim < nch) nch = lim;
    }

    float acc[4][NT][4];
#pragma unroll
    for (int mt = 0; mt < 4; mt++)
#pragma unroll
        for (int nt = 0; nt < NT; nt++)
#pragma unroll
            for (int e = 0; e < 4; e++) acc[mt][nt][e] = 0.0f;

    uint4 ra[APASS], rb[BPASS];

    auto load_regs = [&](int ch) {
        const int kg0 = ch << 5;
#pragma unroll
        for (int p = 0; p < APASS; p++) {
            int idx = p * THREADS + t;
            int r = idx & 127, c = idx >> 7;
            int gr = rowBase + r;
            size_t arow;
            if (MODE == 0) {
                // x rows live inside g_h: beta*2048 + 1024 + (gr & 1023)
                arow = (size_t)(gr + 1024 + ((gr >> 10) << 10));
            } else {
                arow = (size_t)gr;
            }
            ra[p] = *reinterpret_cast<const uint4*>(A + arow * K + kg0 + c * 8);
        }
#pragma unroll
        for (int p = 0; p < BPASS; p++) {
            int idx = p * THREADS + t;
            int r = idx & (BN - 1), c = idx >> LOG2BN;
            rb[p] = *reinterpret_cast<const uint4*>(
                B + (size_t)(colBase + r) * K + kg0 + c * 8);
        }
    };

    auto sts_regs = [&](int buf) {
#pragma unroll
        for (int p = 0; p < APASS; p++) {
            int idx = p * THREADS + t;
            int r = idx & 127, c = idx >> 7;
            *reinterpret_cast<uint4*>(&sA[buf][r * 80 + c * 16]) = ra[p];
        }
#pragma unroll
        for (int p = 0; p < BPASS; p++) {
            int idx = p * THREADS + t;
            int r = idx & (BN - 1), c = idx >> LOG2BN;
            *reinterpret_cast<uint4*>(&sB[buf][r * 80 + c * 16]) = rb[p];
        }
    };

    load_regs(0);
    sts_regs(0);
    __syncthreads();

    const int lrow = (lane & 15) * 80;
    const int kh   = ((lane >> 4) & 1) * 16;

    int buf = 0;
    for (int ch = 0; ch < nch; ch++) {
        if (ch + 1 < nch) load_regs(ch + 1);

        uint32_t aBase = smem_u32(&sA[buf][0]);
        uint32_t bBase = smem_u32(&sB[buf][0]);
#pragma unroll
        for (int ks = 0; ks < 2; ks++) {
            const int kb = ks * 32 + kh;
            uint32_t a[4][4];
#pragma unroll
            for (int mt = 0; mt < 4; mt++)
                ldsm4(a[mt], aBase + (wm * 64 + mt * 16) * 80 + lrow + kb);
            uint32_t bfr[NG][4];
#pragma unroll
            for (int g = 0; g < NG; g++)
                ldsm4(bfr[g], bBase + (wn * WN + g * 16) * 80 + lrow + kb);
#pragma unroll
            for (int mt = 0; mt < 4; mt++)
#pragma unroll
                for (int g = 0; g < NG; g++) {
                    mma16(acc[mt][2 * g],     a[mt], bfr[g][0], bfr[g][2]);
                    mma16(acc[mt][2 * g + 1], a[mt], bfr[g][1], bfr[g][3]);
                }
        }

        if (ch + 1 < nch) {
            __syncthreads();
            sts_regs(buf ^ 1);
            buf ^= 1;
            __syncthreads();
        }
    }

    // ---- epilogue ----
    auto emit = [&](int gr, int gc, float v0, float v1) {
        if (MODE == 0) {
            __nv_bfloat16* A2p = (__nv_bfloat16*)D0v;
            float2 u2 = *reinterpret_cast<const float2*>(aux0 + gc);
            float2 w2 = *reinterpret_cast<const float2*>(aux1 + gc);
            int betaB = gr >> 10, iq = gr & 1023;
            int hh = gc >> 6, d = gc & 63;
            size_t base = ((size_t)(betaB * 16 + hh) * 1024 + iq) * 128 + d;
            uint32_t q  = pack_bf2(v0 + u2.x, v1 + u2.y);
            uint32_t pv = pack_bf2(v0 + w2.x, v1 + w2.y);
            *reinterpret_cast<uint32_t*>(A2p + base) = q;
            if (betaB == 1)
                *reinterpret_cast<uint32_t*>(A2p + base + 64) = pv;
            else if (iq >= 1)
                *reinterpret_cast<uint32_t*>(A2p + base - 64) = pv;
        } else if (MODE == 1) {
            int betaB = gr >> 11, jj = gr & 2047;
            if (gc < 1024) {
                __nv_bfloat16* B2p = (__nv_bfloat16*)D0v;
                int hh = gc >> 6, d = gc & 63;
                *reinterpret_cast<uint32_t*>(
                    B2p + ((size_t)(betaB * 16 + hh) * 2048 + jj) * 128 + d) =
                    pack_bf2(v0, v1);
            } else {
                __nv_bfloat16* Vp = (__nv_bfloat16*)D1v;
                int c = gc - 1024;
                int hh = c >> 6, d = c & 63;
                size_t base = ((size_t)(betaB * 16 + hh) * 64 + d) * 2048 + jj;
                Vp[base]        = __float2bfloat16(v0);
                Vp[base + 2048] = __float2bfloat16(v1);
            }
        } else if (MODE == 2) {
            __nv_bfloat16* Sp = (__nv_bfloat16*)D0v;
            size_t rowb = ((size_t)blockIdx.z * 1024 + gr) * 2048;
            float s0 = (gc + 0 > gr + 1024) ? -1e30f : v0 * 0.125f;
            float s1 = (gc + 1 > gr + 1024) ? -1e30f : v1 * 0.125f;
            *reinterpret_cast<uint32_t*>(Sp + rowb + gc) = pack_bf2(s0, s1);
        } else if (MODE == 3) {
            __nv_bfloat16* Op = (__nv_bfloat16*)D0v;
            int bz = blockIdx.z, beta = bz >> 4, hh = bz & 15;
            *reinterpret_cast<uint32_t*>(
                Op + ((size_t)(beta * 1024 + gr)) * 1024 + hh * 64 + gc) =
                pack_bf2(v0, v1);
        } else {
            float* Yp = (float*)D0v;
            float2 xv = *reinterpret_cast<const float2*>(aux0 + (size_t)gr * 1024 + gc);
            float2 bv = *reinterpret_cast<const float2*>(aux1 + gc);
            *reinterpret_cast<float2*>(Yp + (size_t)gr * 1024 + gc) =
                make_float2(v0 + xv.x + bv.x, v1 + xv.y + bv.y);
        }
    };

#pragma unroll
    for (int mt = 0; mt < 4; mt++) {
#pragma unroll
        for (int nt = 0; nt < NT; nt++) {
            int gr0 = rowBase + wm * 64 + mt * 16 + group;
            int gc  = colBase + wn * WN + nt * 8 + tid4 * 2;
            emit(gr0,     gc, acc[mt][nt][0], acc[mt][nt][1]);
            emit(gr0 + 8, gc, acc[mt][nt][2], acc[mt][nt][3]);
        }
    }
}

// ---------------------------------------------------------------------------
// Two-pass column softmax over query axis i, P written in place (bf16).
// pass1: M, Z over valid i (i >= j-1024). pass2: P = exp(S-M)/Z; zero the
// masked margin [j-1152, j-1024) that G3's chunk granularity can touch.
// ---------------------------------------------------------------------------
__global__ __launch_bounds__(256) void colstats2() {
    int bz = blockIdx.y;
    int j  = blockIdx.x * 256 + threadIdx.x;
    int i0 = j - 1024; if (i0 < 0) i0 = 0;
    __nv_bfloat16* base = g_S + (size_t)bz * 1024 * 2048 + j;

    float m = -CUDART_INF_F;
    float z = 0.0f;
    const __nv_bfloat16* s = base + (size_t)i0 * 2048;
#pragma unroll 4
    for (int i = i0; i < 1024; i++, s += 2048) {
        float v = __bfloat162float(*s);
        float nm = fmaxf(m, v);
        z = z * fexp(m - nm) + fexp(v - nm);
        m = nm;
    }
    float rz = 1.0f / z;

    int iw0 = j - 1152; if (iw0 < 0) iw0 = 0;
    __nv_bfloat16* w = base + (size_t)iw0 * 2048;
    for (int i = iw0; i < i0; i++, w += 2048)
        *w = __float2bfloat16(0.0f);
#pragma unroll 4
    for (int i = i0; i < 1024; i++, w += 2048) {
        float v = __bfloat162float(*w);
        *w = __float2bfloat16(fexp(v - m) * rz);
    }
}

// ---------------------------------------------------------------------------
__global__ __launch_bounds__(256) void ln_kernel(const float* __restrict__ gamma,
                                                 const float* __restrict__ beta,
                                                 float* __restrict__ out) {
    int row = blockIdx.x;
    const float4* yr = reinterpret_cast<const float4*>(g_y + (size_t)row * 1024);
    int t = threadIdx.x;
    float4 v = yr[t];
    float s  = v.x + v.y + v.z + v.w;
    float s2 = v.x * v.x + v.y * v.y + v.z * v.z + v.w * v.w;
#pragma unroll
    for (int off = 16; off; off >>= 1) {
        s  += __shfl_xor_sync(0xFFFFFFFFu, s,  off);
        s2 += __shfl_xor_sync(0xFFFFFFFFu, s2, off);
    }
    __shared__ float shs[8], shs2[8];
    int w = t >> 5, lane = t & 31;
    if (lane == 0) { shs[w] = s; shs2[w] = s2; }
    __syncthreads();
    float ts = 0.0f, ts2 = 0.0f;
#pragma unroll
    for (int i = 0; i < 8; i++) { ts += shs[i]; ts2 += shs2[i]; }
    float mu   = ts * (1.0f / 1024.0f);
    float var  = ts2 * (1.0f / 1024.0f) - mu * mu;
    float rstd = rsqrtf(var + 1e-5f);

    float4 g = reinterpret_cast<const float4*>(gamma)[t];
    float4 b = reinterpret_cast<const float4*>(beta)[t];
    float4 o;
    o.x = (v.x - mu) * rstd * g.x + b.x;
    o.y = (v.y - mu) * rstd * g.y + b.y;
    o.z = (v.z - mu) * rstd * g.z + b.z;
    o.w = (v.w - mu) * rstd * g.w + b.w;
    reinterpret_cast<float4*>(out + (size_t)row * 1024)[t] = o;
}

// ---------------------------------------------------------------------------
extern "C" void kernel_launch(void* const* d_in, const int* in_sizes, int n_in,
                              void* d_out, int out_size) {
    const float* x    = (const float*)d_in[0];
    const float* pos  = (const float*)d_in[1];
    const float* u    = (const float*)d_in[2];
    const float* v    = (const float*)d_in[3];
    const float* mem  = (const float*)d_in[4];
    const float* Wq   = (const float*)d_in[6];
    const float* Wkv  = (const float*)d_in[7];
    const float* Wfc  = (const float*)d_in[8];
    const float* bfc  = (const float*)d_in[9];
    const float* gam  = (const float*)d_in[10];
    const float* bet  = (const float*)d_in[11];
    float* out = (float*)d_out;

    __nv_bfloat16 *A2, *B2, *Vt, *h, *of, *Sp, *Wqb, *Wkvb, *Wfcb;
    float *y;
    cudaGetSymbolAddress((void**)&h,    g_h);
    cudaGetSymbolAddress((void**)&Wqb,  g_Wqb);
    cudaGetSymbolAddress((void**)&Wkvb, g_Wkvb);
    cudaGetSymbolAddress((void**)&Wfcb, g_Wfcb);
    cudaGetSymbolAddress((void**)&A2,   g_A2);
    cudaGetSymbolAddress((void**)&B2,   g_B2);
    cudaGetSymbolAddress((void**)&Vt,   g_V);
    cudaGetSymbolAddress((void**)&of,   g_of);
    cudaGetSymbolAddress((void**)&y,    g_y);
    cudaGetSymbolAddress((void**)&Sp,   g_S);

    cvt_bf16 <<<1024, 256>>>(Wq,  Wqb);
    cvt_bf16 <<<2048, 256>>>(Wkv, Wkvb);
    cvt_bf16 <<<1024, 256>>>(Wfc, Wfcb);
    concat_h <<<4096, 256>>>(x, mem);
    fill_pos <<<4096, 256>>>(pos);
    zero_a2row<<<4, 256>>>();

    // G0: q = x@Wq^T -> A2 (q+u | shifted q+v); A rows remapped into g_h
    gemm_bf16<0, 64, 4><<<dim3(16, 16, 1), 128>>>(h, Wqb, 1024, 0, 0, u, v, A2, nullptr);
    // G1: kv = h@Wkv^T -> B2 k-half + Vt
    gemm_bf16<1, 128, 8><<<dim3(16, 32, 1), 256>>>(h, Wkvb, 1024, 0, 0, nullptr, nullptr, B2, Vt);
    // G2: S = A2@B2^T batched over 32, K=128, mask+scale
    gemm_bf16<2, 128, 8><<<dim3(16, 8, 32), 256>>>(A2, B2, 128,
        (size_t)1024 * 128, (size_t)2048 * 128, nullptr, nullptr, Sp, nullptr);
    // softmax stats + in-place P
    colstats2<<<dim3(8, 32), 256>>>();
    // G3: out = P @ Vt^T (pure bf16)
    gemm_bf16<3, 64, 4><<<dim3(1, 8, 32), 128>>>(Sp, Vt, 2048,
        (size_t)1024 * 2048, (size_t)64 * 2048, nullptr, nullptr, of, nullptr);
    // G4: y = of@Wfc^T + x + bfc
    gemm_bf16<4, 64, 4><<<dim3(16, 16, 1), 128>>>(of, Wfcb, 1024, 0, 0, x, bfc, y, nullptr);
    // LayerNorm
    ln_kernel<<<2048, 256>>>(gam, bet, out);
}

// round 6
// speedup vs baseline: 1.3342x; 1.3342x over previous
#include <cuda_runtime.h>
#include <cuda_bf16.h>
#include <cstdint>
#include <math.h>
#include <math_constants.h>

// ===========================================================================
// RecurrenceAttention — bf16 mma.sync, all-bf16 operands (R4 structure).
//
//  cvt_bf16   : Wq/Wkv/Wfc -> bf16 once (deterministic each call)
//  concat_h   : h = [mem ; x] bf16   (G0 reads x rows out of g_h directly)
//  fill_pos   : B2 pos half ; zero_a2row
//  G0         : q = x@Wq^T   -> A2 bf16 (q+u | shifted q+v)
//  G1         : kv = h@Wkv^T -> B2 bf16 k-half + Vt bf16 ([bz][d][j])
//  G2         : S = A2@B2^T (batched 32, K=128) -> S bf16 (mask+scale);
//               fully-masked tiles skipped (never read downstream)
//  colstats   : per col j: M=max_i S, RZ=1/sum_i exp(S-M) (valid i only)
//  G3         : out = (exp(S-M)*RZ) @ Vt^T, transform fused in A loader,
//               masked K-chunks skipped
//  G4         : y = of@Wfc^T + x + bfc  (fp32 out)
//  ln_kernel  : LayerNorm -> d_out
// ===========================================================================

// ---------------- scratch ----------------
__device__ __nv_bfloat16 g_h   [4096 * 1024];
__device__ __nv_bfloat16 g_Wqb [1024 * 1024];
__device__ __nv_bfloat16 g_Wkvb[2048 * 1024];
__device__ __nv_bfloat16 g_Wfcb[1024 * 1024];
__device__ __nv_bfloat16 g_A2  [32 * 1024 * 128];
__device__ __nv_bfloat16 g_B2  [32 * 2048 * 128];
__device__ __nv_bfloat16 g_V   [32 * 64 * 2048];       // [bz][d][j]
__device__ __nv_bfloat16 g_S   [32u * 1024u * 2048u];
__device__ float g_M  [32 * 2048];
__device__ float g_RZ [32 * 2048];
__device__ __nv_bfloat16 g_of  [2048 * 1024];
__device__ float g_y [2048 * 1024];

// ---------------- helpers ----------------
__device__ __forceinline__ uint32_t smem_u32(const void* p) {
    uint32_t a;
    asm("{ .reg .u64 t; cvta.to.shared.u64 t, %1; cvt.u32.u64 %0, t; }"
        : "=r"(a) : "l"(p));
    return a;
}
__device__ __forceinline__ uint32_t pack_bf2(float a, float b) {
    __nv_bfloat162 h = __float22bfloat162_rn(make_float2(a, b));
    return *reinterpret_cast<uint32_t*>(&h);
}
__device__ __forceinline__ void ldsm4(uint32_t* r, uint32_t addr) {
    asm volatile("ldmatrix.sync.aligned.m8n8.x4.shared.b16 {%0,%1,%2,%3}, [%4];"
                 : "=r"(r[0]), "=r"(r[1]), "=r"(r[2]), "=r"(r[3]) : "r"(addr));
}
__device__ __forceinline__ void mma16(float* c, const uint32_t* a,
                                      uint32_t b0, uint32_t b1) {
    asm volatile(
        "mma.sync.aligned.m16n8k16.row.col.f32.bf16.bf16.f32 "
        "{%0,%1,%2,%3}, {%4,%5,%6,%7}, {%8,%9}, {%0,%1,%2,%3};"
        : "+f"(c[0]), "+f"(c[1]), "+f"(c[2]), "+f"(c[3])
        : "r"(a[0]), "r"(a[1]), "r"(a[2]), "r"(a[3]), "r"(b0), "r"(b1));
}

// fast exp on FMA pipe
__device__ __forceinline__ float fexp(float x) {
    float y = fmaxf(x * 1.4426950408889634f, -126.0f);
    float fn = floorf(y);
    float f  = y - fn;
    float p  = 1.5403530e-4f;
    p = fmaf(p, f, 1.3333558e-3f);
    p = fmaf(p, f, 9.6181291e-3f);
    p = fmaf(p, f, 5.5504109e-2f);
    p = fmaf(p, f, 2.4022651e-1f);
    p = fmaf(p, f, 6.9314718e-1f);
    p = fmaf(p, f, 1.0f);
    return p * __int_as_float(((int)fn + 127) << 23);
}

// ---------------- small kernels ----------------
__global__ __launch_bounds__(256) void cvt_bf16(const float* __restrict__ src,
                                                __nv_bfloat16* __restrict__ dst) {
    size_t i = (size_t)blockIdx.x * 256 + threadIdx.x;
    float4 v = reinterpret_cast<const float4*>(src)[i];
    uint2 o;
    o.x = pack_bf2(v.x, v.y);
    o.y = pack_bf2(v.z, v.w);
    *reinterpret_cast<uint2*>(dst + i * 4) = o;
}

__global__ __launch_bounds__(256) void concat_h(const float* __restrict__ x,
                                                const float* __restrict__ mem) {
    size_t idx = (size_t)blockIdx.x * 256 + threadIdx.x;
    size_t r   = idx >> 8;
    int    c4  = (int)(idx & 255);
    int beta = (int)(r >> 11);
    int s    = (int)(r & 2047);
    const float* src = (s < 1024)
        ? mem + ((size_t)(beta * 1024 + s)) * 1024
        : x   + ((size_t)(beta * 1024 + s - 1024)) * 1024;
    float4 v = reinterpret_cast<const float4*>(src)[c4];
    uint2 o;
    o.x = pack_bf2(v.x, v.y);
    o.y = pack_bf2(v.z, v.w);
    *reinterpret_cast<uint2*>(g_h + idx * 4) = o;
}

__global__ __launch_bounds__(256) void fill_pos(const float* __restrict__ pos_emb) {
    int idx = blockIdx.x * 256 + threadIdx.x;
    int d4 = idx & 15;
    int j  = (idx >> 4) & 2047;
    int bz = idx >> 15;
    int hh = bz & 15;
    float4 p = *reinterpret_cast<const float4*>(pos_emb + (size_t)j * 1024 + hh * 64 + d4 * 4);
    uint2 o;
    o.x = pack_bf2(p.x, p.y);
    o.y = pack_bf2(p.z, p.w);
    *reinterpret_cast<uint2*>(g_B2 + (((size_t)bz * 2048 + j) * 128) + 64 + d4 * 4) = o;
}

__global__ __launch_bounds__(256) void zero_a2row() {
    int t = blockIdx.x * 256 + threadIdx.x;
    int hh = t >> 6, d = t & 63;
    g_A2[(((size_t)hh) * 1024 + 1023) * 128 + 64 + d] = __float2bfloat16(0.0f);
}

// ---------------------------------------------------------------------------
// bf16 GEMM (R4 structure): D(M x N) = A(M x K) * B(N x K)^T, bf16 K-major.
// BM=128, BN=128/64, BK=32. 256 threads, 8 warps 4x2, warp tile 32 x BN/2.
// SMEM rows padded to 80B (conflict-free ldmatrix). Double-buffered.
// MODE: 0=qproj(A rows remapped in g_h)  1=kvproj  2=scores  3=P@V  4=fc
// ---------------------------------------------------------------------------
template <int MODE, int BN>
__global__ __launch_bounds__(256, 2)
void gemm_bf16(const __nv_bfloat16* __restrict__ Ag,
               const __nv_bfloat16* __restrict__ Bg, int K,
               size_t batchA, size_t batchB,
               const float* __restrict__ aux0, const float* __restrict__ aux1,
               void* __restrict__ D0v, void* __restrict__ D1v) {
    constexpr int WN    = BN / 2;
    constexpr int NT    = WN / 8;
    constexpr int NG    = WN / 16;
    constexpr int BPASS = BN / 64;
    constexpr int LOG2BN = (BN == 64) ? 6 : 7;

    __shared__ __align__(16) uint8_t sA[2][128 * 80];
    __shared__ __align__(16) uint8_t sB[2][BN * 80];

    const int t    = threadIdx.x;
    const int wid  = t >> 5;
    const int lane = t & 31;
    const int wm   = wid >> 1;
    const int wn   = wid & 1;
    const int group = lane >> 2;
    const int tid4  = lane & 3;
    const int rowBase = blockIdx.y * 128;
    const int colBase = blockIdx.x * BN;

    // fully-masked score tiles: never read downstream — skip
    if (MODE == 2 && colBase > rowBase + 1151) return;

    const __nv_bfloat16* A = Ag + (size_t)blockIdx.z * batchA;
    const __nv_bfloat16* B = Bg + (size_t)blockIdx.z * batchB;
    const float* Mc = (MODE == 3) ? aux0 + (size_t)blockIdx.z * 2048 : aux0;
    const float* Rc = (MODE == 3) ? aux1 + (size_t)blockIdx.z * 2048 : aux1;

    int nch = K >> 5;
    if (MODE == 3) {
        int lim = ((rowBase + 1151) >> 5) + 1;   // skip fully-masked K-chunks
        if (lim < nch) nch = lim;
    }

    float acc[2][NT][4];
#pragma unroll
    for (int mt = 0; mt < 2; mt++)
#pragma unroll
        for (int nt = 0; nt < NT; nt++)
#pragma unroll
            for (int e = 0; e < 4; e++) acc[mt][nt][e] = 0.0f;

    uint4 ra[2], rb[BPASS];

    auto load_regs = [&](int ch) {
        const int kg0 = ch << 5;
#pragma unroll
        for (int p = 0; p < 2; p++) {
            int idx = p * 256 + t;
            int r = idx & 127, c = idx >> 7;
            int gr = rowBase + r;
            size_t arow = (MODE == 0)
                ? (size_t)(gr + 1024 + ((gr >> 10) << 10))   // x rows inside g_h
                : (size_t)gr;
            int kg = kg0 + c * 8;
            uint4 o = *reinterpret_cast<const uint4*>(A + arow * K + kg);
            if (MODE == 3) {
                float4 m0 = *reinterpret_cast<const float4*>(Mc + kg);
                float4 m1 = *reinterpret_cast<const float4*>(Mc + kg + 4);
                float4 z0 = *reinterpret_cast<const float4*>(Rc + kg);
                float4 z1 = *reinterpret_cast<const float4*>(Rc + kg + 4);
                __nv_bfloat162* hp = reinterpret_cast<__nv_bfloat162*>(&o);
                float2 p0 = __bfloat1622float2(hp[0]);
                float2 p1 = __bfloat1622float2(hp[1]);
                float2 p2 = __bfloat1622float2(hp[2]);
                float2 p3 = __bfloat1622float2(hp[3]);
                o.x = pack_bf2(fexp(p0.x - m0.x) * z0.x, fexp(p0.y - m0.y) * z0.y);
                o.y = pack_bf2(fexp(p1.x - m0.z) * z0.z, fexp(p1.y - m0.w) * z0.w);
                o.z = pack_bf2(fexp(p2.x - m1.x) * z1.x, fexp(p2.y - m1.y) * z1.y);
                o.w = pack_bf2(fexp(p3.x - m1.z) * z1.z, fexp(p3.y - m1.w) * z1.w);
            }
            ra[p] = o;
        }
#pragma unroll
        for (int p = 0; p < BPASS; p++) {
            int idx = p * 256 + t;
            int r = idx & (BN - 1), c = idx >> LOG2BN;
            rb[p] = *reinterpret_cast<const uint4*>(
                B + (size_t)(colBase + r) * K + kg0 + c * 8);
        }
    };

    auto sts_regs = [&](int buf) {
#pragma unroll
        for (int p = 0; p < 2; p++) {
            int idx = p * 256 + t;
            int r = idx & 127, c = idx >> 7;
            *reinterpret_cast<uint4*>(&sA[buf][r * 80 + c * 16]) = ra[p];
        }
#pragma unroll
        for (int p = 0; p < BPASS; p++) {
            int idx = p * 256 + t;
            int r = idx & (BN - 1), c = idx >> LOG2BN;
            *reinterpret_cast<uint4*>(&sB[buf][r * 80 + c * 16]) = rb[p];
        }
    };

    load_regs(0);
    sts_regs(0);
    __syncthreads();

    const int lrow = (lane & 15) * 80;
    const int kh   = ((lane >> 4) & 1) * 16;

    int buf = 0;
    for (int ch = 0; ch < nch; ch++) {
        if (ch + 1 < nch) load_regs(ch + 1);

        uint32_t aBase = smem_u32(&sA[buf][0]);
        uint32_t bBase = smem_u32(&sB[buf][0]);
#pragma unroll
        for (int ks = 0; ks < 2; ks++) {
            const int kb = ks * 32 + kh;
            uint32_t a[2][4];
#pragma unroll
            for (int mt = 0; mt < 2; mt++)
                ldsm4(a[mt], aBase + (wm * 32 + mt * 16) * 80 + lrow + kb);
            uint32_t bfr[NG][4];
#pragma unroll
            for (int g = 0; g < NG; g++)
                ldsm4(bfr[g], bBase + (wn * WN + g * 16) * 80 + lrow + kb);
#pragma unroll
            for (int mt = 0; mt < 2; mt++)
#pragma unroll
                for (int g = 0; g < NG; g++) {
                    mma16(acc[mt][2 * g],     a[mt], bfr[g][0], bfr[g][2]);
                    mma16(acc[mt][2 * g + 1], a[mt], bfr[g][1], bfr[g][3]);
                }
        }

        if (ch + 1 < nch) {
            __syncthreads();
            sts_regs(buf ^ 1);
            buf ^= 1;
            __syncthreads();
        }
    }

    // ---- epilogue ----
    auto emit = [&](int gr, int gc, float v0, float v1) {
        if (MODE == 0) {
            __nv_bfloat16* A2p = (__nv_bfloat16*)D0v;
            float2 u2 = *reinterpret_cast<const float2*>(aux0 + gc);
            float2 w2 = *reinterpret_cast<const float2*>(aux1 + gc);
            int betaB = gr >> 10, iq = gr & 1023;
            int hh = gc >> 6, d = gc & 63;
            size_t base = ((size_t)(betaB * 16 + hh) * 1024 + iq) * 128 + d;
            uint32_t q  = pack_bf2(v0 + u2.x, v1 + u2.y);
            uint32_t pv = pack_bf2(v0 + w2.x, v1 + w2.y);
            *reinterpret_cast<uint32_t*>(A2p + base) = q;
            if (betaB == 1)
                *reinterpret_cast<uint32_t*>(A2p + base + 64) = pv;
            else if (iq >= 1)
                *reinterpret_cast<uint32_t*>(A2p + base - 64) = pv;
        } else if (MODE == 1) {
            int betaB = gr >> 11, jj = gr & 2047;
            if (gc < 1024) {
                __nv_bfloat16* B2p = (__nv_bfloat16*)D0v;
                int hh = gc >> 6, d = gc & 63;
                *reinterpret_cast<uint32_t*>(
                    B2p + ((size_t)(betaB * 16 + hh) * 2048 + jj) * 128 + d) =
                    pack_bf2(v0, v1);
            } else {
                __nv_bfloat16* Vp = (__nv_bfloat16*)D1v;
                int c = gc - 1024;
                int hh = c >> 6, d = c & 63;
                size_t base = ((size_t)(betaB * 16 + hh) * 64 + d) * 2048 + jj;
                Vp[base]        = __float2bfloat16(v0);
                Vp[base + 2048] = __float2bfloat16(v1);
            }
        } else if (MODE == 2) {
            __nv_bfloat16* Sp = (__nv_bfloat16*)D0v;
            size_t rowb = ((size_t)blockIdx.z * 1024 + gr) * 2048;
            float s0 = (gc + 0 > gr + 1024) ? -1e30f : v0 * 0.125f;
            float s1 = (gc + 1 > gr + 1024) ? -1e30f : v1 * 0.125f;
            *reinterpret_cast<uint32_t*>(Sp + rowb + gc) = pack_bf2(s0, s1);
        } else if (MODE == 3) {
            __nv_bfloat16* Op = (__nv_bfloat16*)D0v;
            int bz = blockIdx.z, beta = bz >> 4, hh = bz & 15;
            *reinterpret_cast<uint32_t*>(
                Op + ((size_t)(beta * 1024 + gr)) * 1024 + hh * 64 + gc) =
                pack_bf2(v0, v1);
        } else {
            float* Yp = (float*)D0v;
            float2 xv = *reinterpret_cast<const float2*>(aux0 + (size_t)gr * 1024 + gc);
            float2 bv = *reinterpret_cast<const float2*>(aux1 + gc);
            *reinterpret_cast<float2*>(Yp + (size_t)gr * 1024 + gc) =
                make_float2(v0 + xv.x + bv.x, v1 + xv.y + bv.y);
        }
    };

#pragma unroll
    for (int mt = 0; mt < 2; mt++) {
#pragma unroll
        for (int nt = 0; nt < NT; nt++) {
            int gr0 = rowBase + wm * 32 + mt * 16 + group;
            int gc  = colBase + wn * WN + nt * 8 + tid4 * 2;
            emit(gr0,     gc, acc[mt][nt][0], acc[mt][nt][1]);
            emit(gr0 + 8, gc, acc[mt][nt][2], acc[mt][nt][3]);
        }
    }
}

// ---------------------------------------------------------------------------
// Column softmax stats over query axis i (valid i >= j-1024 only).
// ---------------------------------------------------------------------------
__global__ __launch_bounds__(256) void colstats() {
    int bz = blockIdx.y;
    int j  = blockIdx.x * 256 + threadIdx.x;
    int i0 = j - 1024; if (i0 < 0) i0 = 0;
    const __nv_bfloat16* s = g_S + (size_t)bz * 1024 * 2048 + (size_t)i0 * 2048 + j;
    float m = -CUDART_INF_F;
    float z = 0.0f;
#pragma unroll 4
    for (int i = i0; i < 1024; i++, s += 2048) {
        float v = __bfloat162float(*s);
        float nm = fmaxf(m, v);
        z = z * fexp(m - nm) + fexp(v - nm);
        m = nm;
    }
    g_M [bz * 2048 + j] = m;
    g_RZ[bz * 2048 + j] = 1.0f / z;
}

// ---------------------------------------------------------------------------
__global__ __launch_bounds__(256) void ln_kernel(const float* __restrict__ gamma,
                                                 const float* __restrict__ beta,
                                                 float* __restrict__ out) {
    int row = blockIdx.x;
    const float4* yr = reinterpret_cast<const float4*>(g_y + (size_t)row * 1024);
    int t = threadIdx.x;
    float4 v = yr[t];
    float s  = v.x + v.y + v.z + v.w;
    float s2 = v.x * v.x + v.y * v.y + v.z * v.z + v.w * v.w;
#pragma unroll
    for (int off = 16; off; off >>= 1) {
        s  += __shfl_xor_sync(0xFFFFFFFFu, s,  off);
        s2 += __shfl_xor_sync(0xFFFFFFFFu, s2, off);
    }
    __shared__ float shs[8], shs2[8];
    int w = t >> 5, lane = t & 31;
    if (lane == 0) { shs[w] = s; shs2[w] = s2; }
    __syncthreads();
    float ts = 0.0f, ts2 = 0.0f;
#pragma unroll
    for (int i = 0; i < 8; i++) { ts += shs[i]; ts2 += shs2[i]; }
    float mu   = ts * (1.0f / 1024.0f);
    float var  = ts2 * (1.0f / 1024.0f) - mu * mu;
    float rstd = rsqrtf(var + 1e-5f);

    float4 g = reinterpret_cast<const float4*>(gamma)[t];
    float4 b = reinterpret_cast<const float4*>(beta)[t];
    float4 o;
    o.x = (v.x - mu) * rstd * g.x + b.x;
    o.y = (v.y - mu) * rstd * g.y + b.y;
    o.z = (v.z - mu) * rstd * g.z + b.z;
    o.w = (v.w - mu) * rstd * g.w + b.w;
    reinterpret_cast<float4*>(out + (size_t)row * 1024)[t] = o;
}

// ---------------------------------------------------------------------------
extern "C" void kernel_launch(void* const* d_in, const int* in_sizes, int n_in,
                              void* d_out, int out_size) {
    const float* x    = (const float*)d_in[0];
    const float* pos  = (const float*)d_in[1];
    const float* u    = (const float*)d_in[2];
    const float* v    = (const float*)d_in[3];
    const float* mem  = (const float*)d_in[4];
    const float* Wq   = (const float*)d_in[6];
    const float* Wkv  = (const float*)d_in[7];
    const float* Wfc  = (const float*)d_in[8];
    const float* bfc  = (const float*)d_in[9];
    const float* gam  = (const float*)d_in[10];
    const float* bet  = (const float*)d_in[11];
    float* out = (float*)d_out;

    __nv_bfloat16 *A2, *B2, *Vt, *h, *of, *Sp, *Wqb, *Wkvb, *Wfcb;
    float *y, *Mp, *Rp;
    cudaGetSymbolAddress((void**)&h,    g_h);
    cudaGetSymbolAddress((void**)&Wqb,  g_Wqb);
    cudaGetSymbolAddress((void**)&Wkvb, g_Wkvb);
    cudaGetSymbolAddress((void**)&Wfcb, g_Wfcb);
    cudaGetSymbolAddress((void**)&A2,   g_A2);
    cudaGetSymbolAddress((void**)&B2,   g_B2);
    cudaGetSymbolAddress((void**)&Vt,   g_V);
    cudaGetSymbolAddress((void**)&of,   g_of);
    cudaGetSymbolAddress((void**)&y,    g_y);
    cudaGetSymbolAddress((void**)&Sp,   g_S);
    cudaGetSymbolAddress((void**)&Mp,   g_M);
    cudaGetSymbolAddress((void**)&Rp,   g_RZ);

    cvt_bf16 <<<1024, 256>>>(Wq,  Wqb);
    cvt_bf16 <<<2048, 256>>>(Wkv, Wkvb);
    cvt_bf16 <<<1024, 256>>>(Wfc, Wfcb);
    concat_h <<<4096, 256>>>(x, mem);
    fill_pos <<<4096, 256>>>(pos);
    zero_a2row<<<4, 256>>>();

    // G0: q = x@Wq^T -> A2 (q+u | shifted q+v); A rows remapped into g_h
    gemm_bf16<0, 64><<<dim3(16, 16, 1), 256>>>(h, Wqb, 1024, 0, 0, u, v, A2, nullptr);
    // G1: kv = h@Wkv^T -> B2 k-half + Vt
    gemm_bf16<1, 128><<<dim3(16, 32, 1), 256>>>(h, Wkvb, 1024, 0, 0, nullptr, nullptr, B2, Vt);
    // G2: S = A2@B2^T batched over 32, K=128, mask+scale
    gemm_bf16<2, 128><<<dim3(16, 8, 32), 256>>>(A2, B2, 128,
        (size_t)1024 * 128, (size_t)2048 * 128, nullptr, nullptr, Sp, nullptr);
    // softmax stats over query axis
    colstats<<<dim3(8, 32), 256>>>();
    // G3: out = (exp(S-M)*RZ) @ Vt^T
    gemm_bf16<3, 64><<<dim3(1, 8, 32), 256>>>(Sp, Vt, 2048,
        (size_t)1024 * 2048, (size_t)64 * 2048, Mp, Rp, of, nullptr);
    // G4: y = of@Wfc^T + x + bfc
    gemm_bf16<4, 64><<<dim3(16, 16, 1), 256>>>(of, Wfcb, 1024, 0, 0, x, bfc, y, nullptr);
    // LayerNorm
    ln_kernel<<<2048, 256>>>(gam, bet, out);
}